// round 1
// baseline (speedup 1.0000x reference)
#include <cuda_runtime.h>

#define BB 8
#define TT 128
#define DD 512
#define MM (BB*TT)          // 1024 tokens
#define NWT 6               // qf,kf,vf,qt,kt,vt

// 6 * 1024 * 512 floats = 12.6 MB scratch for the projections
__device__ float g_proj[NWT * MM * DD];

struct WPtrs {
    const float* W[NWT];
    const float* b[NWT];
};

// ---------------------------------------------------------------------------
// Kernel 1: fused projection GEMM.
// out[w][m][o] = sum_k x[m][k] * W_w[o][k] + b_w[o]
// Treated as one [M=1024, N=6*512=3072] GEMM, K=512, both operands K-contiguous.
// 64x64 CTA tile, 32-wide K tile, 256 threads, 4x4 register micro-tile.
// ---------------------------------------------------------------------------
__global__ __launch_bounds__(256) void proj_gemm(const float* __restrict__ x, WPtrs p) {
    __shared__ float As[32][64];
    __shared__ float Bs[32][64];

    const int m0 = blockIdx.x * 64;
    const int ng = blockIdx.y * 64;     // global n in [0, 3072)
    const int w  = ng / DD;             // which weight matrix (tile never spans two)
    const int o0 = ng % DD;
    const float* __restrict__ Wm = p.W[w];
    const float* __restrict__ bv = p.b[w];

    const int tid = threadIdx.x;
    const int lm  = tid & 63;           // row within tile for loads
    const int kq0 = tid >> 6;           // 0..3 : float4 group along K
    const int tx  = tid & 15;           // micro-tile n
    const int ty  = tid >> 4;           // micro-tile m

    float acc[4][4];
    #pragma unroll
    for (int i = 0; i < 4; i++)
        #pragma unroll
        for (int j = 0; j < 4; j++) acc[i][j] = 0.f;

    for (int k0 = 0; k0 < DD; k0 += 32) {
        #pragma unroll
        for (int r = 0; r < 2; r++) {
            const int kq = kq0 + r * 4;  // 0..7
            float4 av = *(const float4*)&x [(size_t)(m0 + lm) * DD + k0 + kq * 4];
            float4 bw = *(const float4*)&Wm[(size_t)(o0 + lm) * DD + k0 + kq * 4];
            As[kq*4+0][lm] = av.x; As[kq*4+1][lm] = av.y;
            As[kq*4+2][lm] = av.z; As[kq*4+3][lm] = av.w;
            Bs[kq*4+0][lm] = bw.x; Bs[kq*4+1][lm] = bw.y;
            Bs[kq*4+2][lm] = bw.z; Bs[kq*4+3][lm] = bw.w;
        }
        __syncthreads();

        #pragma unroll
        for (int kk = 0; kk < 32; kk++) {
            float4 a = *(const float4*)&As[kk][ty * 4];
            float4 b = *(const float4*)&Bs[kk][tx * 4];
            acc[0][0] = fmaf(a.x, b.x, acc[0][0]);
            acc[0][1] = fmaf(a.x, b.y, acc[0][1]);
            acc[0][2] = fmaf(a.x, b.z, acc[0][2]);
            acc[0][3] = fmaf(a.x, b.w, acc[0][3]);
            acc[1][0] = fmaf(a.y, b.x, acc[1][0]);
            acc[1][1] = fmaf(a.y, b.y, acc[1][1]);
            acc[1][2] = fmaf(a.y, b.z, acc[1][2]);
            acc[1][3] = fmaf(a.y, b.w, acc[1][3]);
            acc[2][0] = fmaf(a.z, b.x, acc[2][0]);
            acc[2][1] = fmaf(a.z, b.y, acc[2][1]);
            acc[2][2] = fmaf(a.z, b.z, acc[2][2]);
            acc[2][3] = fmaf(a.z, b.w, acc[2][3]);
            acc[3][0] = fmaf(a.w, b.x, acc[3][0]);
            acc[3][1] = fmaf(a.w, b.y, acc[3][1]);
            acc[3][2] = fmaf(a.w, b.z, acc[3][2]);
            acc[3][3] = fmaf(a.w, b.w, acc[3][3]);
        }
        __syncthreads();
    }

    const float4 bias4 = *(const float4*)&bv[o0 + tx * 4];
    #pragma unroll
    for (int ii = 0; ii < 4; ii++) {
        const int m = m0 + ty * 4 + ii;
        float4 r;
        r.x = acc[ii][0] + bias4.x;
        r.y = acc[ii][1] + bias4.y;
        r.z = acc[ii][2] + bias4.z;
        r.w = acc[ii][3] + bias4.w;
        *(float4*)&g_proj[((size_t)w * MM + m) * DD + o0 + tx * 4] = r;
    }
}

// ---------------------------------------------------------------------------
// Kernel 2: per-token fused feature + temporal branch.
// One CTA per token (1024 CTAs), 512 threads (thread i = feature index i).
//
// Feature:  ctx_f_i = softmax_i(Qf .* Kf) * Vf_i
// Temporal: scores row i is Qt_i * Kt  (rank-1!), so
//           row max = Qt_i>=0 ? Qt_i*max(Kt) : Qt_i*min(Kt)
//           ctx_t_i = sum_j exp(Qt_i*Kt_j - m_i) * Vt_j / sum_j exp(...)
// ---------------------------------------------------------------------------
__global__ __launch_bounds__(512) void attn_kernel(float* __restrict__ out) {
    const int m    = blockIdx.x;
    const int i    = threadIdx.x;
    const int lane = i & 31;
    const int wid  = i >> 5;     // 16 warps

    const float* __restrict__ Qf = g_proj + (size_t)0 * MM * DD + (size_t)m * DD;
    const float* __restrict__ Kf = g_proj + (size_t)1 * MM * DD + (size_t)m * DD;
    const float* __restrict__ Vf = g_proj + (size_t)2 * MM * DD + (size_t)m * DD;
    const float* __restrict__ Qt = g_proj + (size_t)3 * MM * DD + (size_t)m * DD;
    const float* __restrict__ Kt = g_proj + (size_t)4 * MM * DD + (size_t)m * DD;
    const float* __restrict__ Vt = g_proj + (size_t)5 * MM * DD + (size_t)m * DD;

    __shared__ __align__(16) float sK[DD];
    __shared__ __align__(16) float sV[DD];
    __shared__ float redA[16], redB[16], redC[16];

    const float kt = Kt[i];
    const float vt = Vt[i];
    sK[i] = kt;
    sV[i] = vt;
    const float s  = Qf[i] * Kf[i];
    const float vf = Vf[i];
    const float c  = Qt[i];

    // joint warp reduction: max(s), max(kt), min(kt)
    float smax = s, kmax = kt, kmin = kt;
    #pragma unroll
    for (int off = 16; off; off >>= 1) {
        smax = fmaxf(smax, __shfl_xor_sync(0xffffffffu, smax, off));
        kmax = fmaxf(kmax, __shfl_xor_sync(0xffffffffu, kmax, off));
        kmin = fminf(kmin, __shfl_xor_sync(0xffffffffu, kmin, off));
    }
    if (lane == 0) { redA[wid] = smax; redB[wid] = kmax; redC[wid] = kmin; }
    __syncthreads();   // also publishes sK / sV

    smax = redA[0]; kmax = redB[0]; kmin = redC[0];
    #pragma unroll
    for (int t = 1; t < 16; t++) {
        smax = fmaxf(smax, redA[t]);
        kmax = fmaxf(kmax, redB[t]);
        kmin = fminf(kmin, redC[t]);
    }
    __syncthreads();   // protect redA before reuse

    // feature-branch softmax denominator
    const float e = __expf(s - smax);
    float zf = e;
    #pragma unroll
    for (int off = 16; off; off >>= 1)
        zf += __shfl_xor_sync(0xffffffffu, zf, off);
    if (lane == 0) redA[wid] = zf;
    __syncthreads();
    zf = redA[0];
    #pragma unroll
    for (int t = 1; t < 16; t++) zf += redA[t];

    const float ctx_f = (e / zf) * vf;

    // temporal branch: per-thread scalar c against the whole Kt/Vt row
    const float mexp = (c >= 0.f) ? c * kmax : c * kmin;   // exact row max
    float Z = 0.f, S = 0.f;
    #pragma unroll 4
    for (int j = 0; j < DD; j += 4) {
        const float4 k4 = *(const float4*)&sK[j];
        const float4 v4 = *(const float4*)&sV[j];
        const float e0 = __expf(fmaf(c, k4.x, -mexp));
        const float e1 = __expf(fmaf(c, k4.y, -mexp));
        const float e2 = __expf(fmaf(c, k4.z, -mexp));
        const float e3 = __expf(fmaf(c, k4.w, -mexp));
        Z += (e0 + e1) + (e2 + e3);
        S = fmaf(e0, v4.x, S);
        S = fmaf(e1, v4.y, S);
        S = fmaf(e2, v4.z, S);
        S = fmaf(e3, v4.w, S);
    }

    out[(size_t)m * DD + i] = ctx_f + S / Z;
}

extern "C" void kernel_launch(void* const* d_in, const int* in_sizes, int n_in,
                              void* d_out, int out_size) {
    (void)in_sizes; (void)n_in; (void)out_size;
    const float* x = (const float*)d_in[0];
    WPtrs p;
    for (int w = 0; w < NWT; w++) {
        p.W[w] = (const float*)d_in[1 + 2 * w];
        p.b[w] = (const float*)d_in[2 + 2 * w];
    }
    dim3 g1(MM / 64, (NWT * DD) / 64);   // 16 x 48
    proj_gemm<<<g1, 256>>>(x, p);
    attn_kernel<<<MM, 512>>>((float*)d_out);
}

// round 3
// speedup vs baseline: 1.7338x; 1.7338x over previous
#include <cuda_runtime.h>
#include <cuda_bf16.h>
#include <cstdint>

#define BB 8
#define TT 128
#define DD 512
#define MM (BB*TT)          // 1024 tokens
#define NWT 6
#define NN (NWT*DD)         // 3072 total output cols
#define KP 1536             // split-K': [hi|hi|lo] x [hi|lo|hi]
#define KC 64               // K-chunk (64 bf16 = 128B = swizzle-atom row)
#define NCH (KP/KC)         // 24 chunks
#define MT 128
#define NT 128
#define GSMEM (64*1024)

__device__ float g_proj[NWT * MM * DD];          // 12 MB fp32 projections
__device__ __nv_bfloat16 gA[(size_t)MM * KP];    // 3 MB packed A'
__device__ __nv_bfloat16 gB[(size_t)NN * KP];    // 9 MB packed B'

struct WPtrs { const float* W[NWT]; const float* b[NWT]; };

// ---------------------------------------------------------------------------
// helpers (family-agnostic PTX only: cp.async / ldmatrix / mma.sync / ex2)
// ---------------------------------------------------------------------------
__device__ __forceinline__ uint32_t smem_u32(const void* p) {
    uint32_t a;
    asm("{ .reg .u64 t; cvta.to.shared.u64 t, %1; cvt.u32.u64 %0, t; }" : "=r"(a) : "l"(p));
    return a;
}
__device__ __forceinline__ void cp16(uint32_t saddr, const void* g) {
    asm volatile("cp.async.cg.shared.global [%0], [%1], 16;" :: "r"(saddr), "l"(g));
}
__device__ __forceinline__ void cp_commit() { asm volatile("cp.async.commit_group;" ::: "memory"); }
__device__ __forceinline__ void cp_wait1()  { asm volatile("cp.async.wait_group 1;" ::: "memory"); }
__device__ __forceinline__ void cp_wait0()  { asm volatile("cp.async.wait_group 0;" ::: "memory"); }
__device__ __forceinline__ void ldsm4(uint32_t* d, uint32_t a) {
    asm volatile("ldmatrix.sync.aligned.m8n8.x4.shared.b16 {%0,%1,%2,%3}, [%4];"
        : "=r"(d[0]), "=r"(d[1]), "=r"(d[2]), "=r"(d[3]) : "r"(a));
}
__device__ __forceinline__ void mma16816(float* c, const uint32_t* a, uint32_t b0, uint32_t b1) {
    asm volatile(
        "mma.sync.aligned.m16n8k16.row.col.f32.bf16.bf16.f32 "
        "{%0,%1,%2,%3}, {%4,%5,%6,%7}, {%8,%9}, {%0,%1,%2,%3};"
        : "+f"(c[0]), "+f"(c[1]), "+f"(c[2]), "+f"(c[3])
        : "r"(a[0]), "r"(a[1]), "r"(a[2]), "r"(a[3]), "r"(b0), "r"(b1));
}
__device__ __forceinline__ float ex2f(float x) { float y; asm("ex2.approx.f32 %0, %1;" : "=f"(y) : "f"(x)); return y; }

#define SW128(o) ((o) ^ (((o) >> 3) & 0x70))

// ---------------------------------------------------------------------------
// fp32 -> bf16 hi/lo split & pack
// A' cols: [0,512)=x_hi  [512,1024)=x_hi  [1024,1536)=x_lo
// B' cols: [0,512)=W_hi  [512,1024)=W_lo  [1024,1536)=W_hi
// ---------------------------------------------------------------------------
__global__ __launch_bounds__(256) void conv_x(const float* __restrict__ x) {
    int idx = blockIdx.x * 256 + threadIdx.x;        // < 131072
    int m = idx >> 7;
    int k4 = (idx & 127) << 2;
    float4 v = *(const float4*)&x[(size_t)m * DD + k4];
    __nv_bfloat16 h[4], l[4];
    float vv[4] = {v.x, v.y, v.z, v.w};
    #pragma unroll
    for (int i = 0; i < 4; i++) {
        h[i] = __float2bfloat16_rn(vv[i]);
        l[i] = __float2bfloat16_rn(vv[i] - __bfloat162float(h[i]));
    }
    __nv_bfloat162* p0 = (__nv_bfloat162*)&gA[(size_t)m * KP + k4];
    p0[0] = {h[0], h[1]}; p0[1] = {h[2], h[3]};
    __nv_bfloat162* p1 = (__nv_bfloat162*)&gA[(size_t)m * KP + 512 + k4];
    p1[0] = {h[0], h[1]}; p1[1] = {h[2], h[3]};
    __nv_bfloat162* p2 = (__nv_bfloat162*)&gA[(size_t)m * KP + 1024 + k4];
    p2[0] = {l[0], l[1]}; p2[1] = {l[2], l[3]};
}

__global__ __launch_bounds__(256) void conv_w(WPtrs p) {
    int idx = blockIdx.x * 256 + threadIdx.x;        // < 393216
    int flat = idx << 2;
    int w = flat >> 18;
    int o = (flat >> 9) & 511;
    int k4 = flat & 511;
    float4 v = *(const float4*)&p.W[w][(size_t)o * DD + k4];
    __nv_bfloat16 h[4], l[4];
    float vv[4] = {v.x, v.y, v.z, v.w};
    #pragma unroll
    for (int i = 0; i < 4; i++) {
        h[i] = __float2bfloat16_rn(vv[i]);
        l[i] = __float2bfloat16_rn(vv[i] - __bfloat162float(h[i]));
    }
    size_t row = (size_t)(w * DD + o) * KP;
    __nv_bfloat162* p0 = (__nv_bfloat162*)&gB[row + k4];
    p0[0] = {h[0], h[1]}; p0[1] = {h[2], h[3]};
    __nv_bfloat162* p1 = (__nv_bfloat162*)&gB[row + 512 + k4];
    p1[0] = {l[0], l[1]}; p1[1] = {l[2], l[3]};
    __nv_bfloat162* p2 = (__nv_bfloat162*)&gB[row + 1024 + k4];
    p2[0] = {h[0], h[1]}; p2[1] = {h[2], h[3]};
}

// ---------------------------------------------------------------------------
// mma.sync GEMM: D[1024,3072] = A'[1024,1536] @ B'[3072,1536]^T + bias
// 128x128 CTA tile, 8 warps (4 m-rows x 2 n-cols), warp tile 32x64.
// ---------------------------------------------------------------------------
__device__ __forceinline__ void load_chunk(int tid, int m0, int ng, int c,
                                           uint32_t sAb, uint32_t sBb) {
    const int kb = c * KC;
    #pragma unroll
    for (int t = 0; t < 4; t++) {
        int idx = tid + t * 256;
        int row = idx >> 3, c16 = idx & 7;
        const char* ga = (const char*)gA + ((size_t)(m0 + row) * KP + kb) * 2 + c16 * 16;
        cp16(sAb + SW128(row * 128 + c16 * 16), ga);
    }
    #pragma unroll
    for (int t = 0; t < 4; t++) {
        int idx = tid + t * 256;
        int row = idx >> 3, c16 = idx & 7;
        const char* gb = (const char*)gB + ((size_t)(ng + row) * KP + kb) * 2 + c16 * 16;
        cp16(sBb + SW128(row * 128 + c16 * 16), gb);
    }
    cp_commit();
}

__global__ __launch_bounds__(256, 2) void gemm_mma(WPtrs p) {
    extern __shared__ __align__(1024) char dsm[];
    const uint32_t sbase = smem_u32(dsm);
    const uint32_t sA[2] = {sbase,            sbase + 16384u};
    const uint32_t sB[2] = {sbase + 32768u,   sbase + 49152u};

    const int tid  = threadIdx.x;
    const int wid  = tid >> 5, lane = tid & 31;
    const int wm   = wid & 3;        // m offset = wm*32
    const int wn   = wid >> 2;       // n offset = wn*64
    const int m0 = blockIdx.x * MT;
    const int ng = blockIdx.y * NT;

    float acc[2][8][4];
    #pragma unroll
    for (int i = 0; i < 2; i++)
        #pragma unroll
        for (int j = 0; j < 8; j++)
            #pragma unroll
            for (int q = 0; q < 4; q++) acc[i][j][q] = 0.f;

    load_chunk(tid, m0, ng, 0, sA[0], sB[0]);
    load_chunk(tid, m0, ng, 1, sA[1], sB[1]);

    // precompute per-thread ldmatrix byte offsets (within a 128x128B tile)
    const int a_row  = wm * 32 + (lane & 15);
    const int a_koff = ((lane >> 4) << 3) * 2;          // bytes
    const int b_row  = wn * 64 + (lane & 7) + ((lane >> 4) << 3);
    const int b_koff = (((lane >> 3) & 1) << 3) * 2;    // bytes

    for (int ch = 0; ch < NCH; ch++) {
        const int buf = ch & 1;
        if (ch < NCH - 1) cp_wait1(); else cp_wait0();
        __syncthreads();

        #pragma unroll
        for (int ks = 0; ks < 4; ks++) {
            const int kb = ks * 32;  // bytes (16 bf16)
            uint32_t a[2][4];
            #pragma unroll
            for (int mt = 0; mt < 2; mt++)
                ldsm4(a[mt], sA[buf] + SW128((a_row + mt * 16) * 128 + kb + a_koff));
            uint32_t b[4][4];
            #pragma unroll
            for (int nt = 0; nt < 4; nt++)
                ldsm4(b[nt], sB[buf] + SW128((b_row + nt * 16) * 128 + kb + b_koff));
            #pragma unroll
            for (int mt = 0; mt < 2; mt++)
                #pragma unroll
                for (int nb = 0; nb < 8; nb++)
                    mma16816(acc[mt][nb], a[mt], b[nb >> 1][(nb & 1) * 2], b[nb >> 1][(nb & 1) * 2 + 1]);
        }
        __syncthreads();
        if (ch + 2 < NCH) load_chunk(tid, m0, ng, ch + 2, sA[buf], sB[buf]);
    }

    // epilogue: + bias, write fp32 projections
    const int w  = ng >> 9;
    const int o0 = (ng & 511) + wn * 64;
    const float* __restrict__ bv = p.b[w];
    const int qrow = lane >> 2;
    const int qcol = (lane & 3) * 2;
    #pragma unroll
    for (int mt = 0; mt < 2; mt++) {
        const int r0 = m0 + wm * 32 + mt * 16 + qrow;
        #pragma unroll
        for (int nb = 0; nb < 8; nb++) {
            const int col = o0 + nb * 8 + qcol;
            const float2 b2 = *(const float2*)&bv[col];
            float* d0 = &g_proj[((size_t)w * MM + r0) * DD + col];
            float* d1 = &g_proj[((size_t)w * MM + r0 + 8) * DD + col];
            ((float2*)d0)[0] = {acc[mt][nb][0] + b2.x, acc[mt][nb][1] + b2.y};
            ((float2*)d1)[0] = {acc[mt][nb][2] + b2.x, acc[mt][nb][3] + b2.y};
        }
    }
}

// ---------------------------------------------------------------------------
// Per-token fused feature + temporal branch (exp folded to ex2)
// ---------------------------------------------------------------------------
__global__ __launch_bounds__(512) void attn_kernel(float* __restrict__ out) {
    const int m    = blockIdx.x;
    const int i    = threadIdx.x;
    const int lane = i & 31;
    const int wid  = i >> 5;
    const float LOG2E = 1.4426950408889634f;

    const float* __restrict__ Qf = g_proj + (size_t)0 * MM * DD + (size_t)m * DD;
    const float* __restrict__ Kf = g_proj + (size_t)1 * MM * DD + (size_t)m * DD;
    const float* __restrict__ Vf = g_proj + (size_t)2 * MM * DD + (size_t)m * DD;
    const float* __restrict__ Qt = g_proj + (size_t)3 * MM * DD + (size_t)m * DD;
    const float* __restrict__ Kt = g_proj + (size_t)4 * MM * DD + (size_t)m * DD;
    const float* __restrict__ Vt = g_proj + (size_t)5 * MM * DD + (size_t)m * DD;

    __shared__ __align__(16) float sK[DD];
    __shared__ __align__(16) float sV[DD];
    __shared__ float redA[16], redB[16], redC[16];

    const float kt = Kt[i];
    const float vt = Vt[i];
    sK[i] = kt;
    sV[i] = vt;
    const float s  = Qf[i] * Kf[i];
    const float vf = Vf[i];
    const float c  = Qt[i];

    float smax = s, kmax = kt, kmin = kt;
    #pragma unroll
    for (int off = 16; off; off >>= 1) {
        smax = fmaxf(smax, __shfl_xor_sync(0xffffffffu, smax, off));
        kmax = fmaxf(kmax, __shfl_xor_sync(0xffffffffu, kmax, off));
        kmin = fminf(kmin, __shfl_xor_sync(0xffffffffu, kmin, off));
    }
    if (lane == 0) { redA[wid] = smax; redB[wid] = kmax; redC[wid] = kmin; }
    __syncthreads();
    smax = redA[0]; kmax = redB[0]; kmin = redC[0];
    #pragma unroll
    for (int t = 1; t < 16; t++) {
        smax = fmaxf(smax, redA[t]);
        kmax = fmaxf(kmax, redB[t]);
        kmin = fminf(kmin, redC[t]);
    }
    __syncthreads();

    const float e = ex2f((s - smax) * LOG2E);
    float zf = e;
    #pragma unroll
    for (int off = 16; off; off >>= 1)
        zf += __shfl_xor_sync(0xffffffffu, zf, off);
    if (lane == 0) redA[wid] = zf;
    __syncthreads();
    zf = redA[0];
    #pragma unroll
    for (int t = 1; t < 16; t++) zf += redA[t];

    const float ctx_f = (e / zf) * vf;

    const float c2 = c * LOG2E;
    const float m2 = (c >= 0.f) ? c2 * kmax : c2 * kmin;
    const float nm2 = -m2;
    float Z = 0.f, S = 0.f;
    #pragma unroll 4
    for (int j = 0; j < DD; j += 4) {
        const float4 k4 = *(const float4*)&sK[j];
        const float4 v4 = *(const float4*)&sV[j];
        const float e0 = ex2f(fmaf(c2, k4.x, nm2));
        const float e1 = ex2f(fmaf(c2, k4.y, nm2));
        const float e2 = ex2f(fmaf(c2, k4.z, nm2));
        const float e3 = ex2f(fmaf(c2, k4.w, nm2));
        Z += (e0 + e1) + (e2 + e3);
        S = fmaf(e0, v4.x, S);
        S = fmaf(e1, v4.y, S);
        S = fmaf(e2, v4.z, S);
        S = fmaf(e3, v4.w, S);
    }

    out[(size_t)m * DD + i] = ctx_f + S / Z;
}

extern "C" void kernel_launch(void* const* d_in, const int* in_sizes, int n_in,
                              void* d_out, int out_size) {
    (void)in_sizes; (void)n_in; (void)out_size;
    const float* x = (const float*)d_in[0];
    WPtrs p;
    for (int w = 0; w < NWT; w++) {
        p.W[w] = (const float*)d_in[1 + 2 * w];
        p.b[w] = (const float*)d_in[2 + 2 * w];
    }
    cudaFuncSetAttribute(gemm_mma, cudaFuncAttributeMaxDynamicSharedMemorySize, GSMEM);
    conv_x<<<512, 256>>>(x);
    conv_w<<<1536, 256>>>(p);
    gemm_mma<<<dim3(MM / MT, NN / NT), 256, GSMEM>>>(p);
    attn_kernel<<<MM, 512>>>((float*)d_out);
}